// round 11
// baseline (speedup 1.0000x reference)
#include <cuda_runtime.h>
#include <cuda_fp16.h>
#include <cstdint>
#include <cstddef>

#define B_  64
#define T_  1024
#define F_  512
#define H_  512
#define G4_ 2048   // 4H
#define NCTA 128

__device__ float  g_xproj[(size_t)T_ * B_ * G4_];        // [t][b][col] fp32
__device__ __half g_hbufh[2][H_ * B_];                   // [col(k)][b] fp16, double-buffered
__device__ unsigned g_flags[NCTA * 32];                  // 1 flag per 128B line
__device__ __half g_ah[(size_t)B_ * T_ * F_];            // inputs as fp16 [m][k]
__device__ __half g_bh[(size_t)G4_ * F_];                // Wx^T fp16 [n][k]

// ---------------------------------------------------------------------------
// helpers
// ---------------------------------------------------------------------------
__device__ __forceinline__ void cp16(void* dst, const void* src)
{
    unsigned d = (unsigned)__cvta_generic_to_shared(dst);
    asm volatile("cp.async.cg.shared.global [%0], [%1], 16;" :: "r"(d), "l"(src) : "memory");
}

__device__ __forceinline__ unsigned ld_acq(const unsigned* p)
{
    unsigned v;
    asm volatile("ld.acquire.gpu.global.u32 %0, [%1];" : "=r"(v) : "l"(p) : "memory");
    return v;
}

__device__ __forceinline__ void st_rel(unsigned* p, unsigned v)
{
    asm volatile("st.release.gpu.global.u32 [%0], %1;" :: "l"(p), "r"(v) : "memory");
}

__device__ __forceinline__ unsigned pack2(float a, float b)
{
    __half2 h = __floats2half2_rn(a, b);
    return *(unsigned*)&h;
}

// lo part of the tf32 split: x - truncate_to_tf32(x)  (exact in fp32)
__device__ __forceinline__ float tf32_lo(float x)
{
    unsigned u = __float_as_uint(x) & 0xFFFFE000u;
    return x - __uint_as_float(u);
}

__device__ __forceinline__ void mma8(float* c,
    unsigned a0, unsigned a1, unsigned a2, unsigned a3,
    unsigned b0, unsigned b1)
{
    asm volatile(
        "mma.sync.aligned.m16n8k8.row.col.f32.tf32.tf32.f32 "
        "{%0,%1,%2,%3}, {%4,%5,%6,%7}, {%8,%9}, {%0,%1,%2,%3};"
        : "+f"(c[0]), "+f"(c[1]), "+f"(c[2]), "+f"(c[3])
        : "r"(a0), "r"(a1), "r"(a2), "r"(a3), "r"(b0), "r"(b1));
}

__device__ __forceinline__ void mma16(float* c,
    unsigned a0, unsigned a1, unsigned a2, unsigned a3,
    unsigned b0, unsigned b1)
{
    asm volatile(
        "mma.sync.aligned.m16n8k16.row.col.f32.f16.f16.f32 "
        "{%0,%1,%2,%3}, {%4,%5,%6,%7}, {%8,%9}, {%0,%1,%2,%3};"
        : "+f"(c[0]), "+f"(c[1]), "+f"(c[2]), "+f"(c[3])
        : "r"(a0), "r"(a1), "r"(a2), "r"(a3), "r"(b0), "r"(b1));
}

__device__ __forceinline__ void ldmx4(unsigned* r, unsigned addr)
{
    asm volatile(
        "ldmatrix.sync.aligned.m8n8.x4.shared.b16 {%0,%1,%2,%3}, [%4];"
        : "=r"(r[0]), "=r"(r[1]), "=r"(r[2]), "=r"(r[3]) : "r"(addr));
}

__device__ __forceinline__ uint32_t smem_to_u32(const void* p) {
    uint32_t a;
    asm("{ .reg .u64 t; cvta.to.shared.u64 t, %1; cvt.u32.u64 %0, t; }"
        : "=r"(a) : "l"(p));
    return a;
}

// ---------------------------------------------------------------------------
// Prep kernels: inputs -> fp16 [m][k]; Wx -> transposed fp16 [n][k]
// ---------------------------------------------------------------------------
__global__ void __launch_bounds__(256) conv_a(const float* __restrict__ A)
{
    unsigned i0 = blockIdx.x * 256 + threadIdx.x;
#pragma unroll
    for (int j = 0; j < 8; j++) {
        unsigned i = i0 + j * (8192u * 256u);
        float2 v = ((const float2*)A)[i];
        ((unsigned*)g_ah)[i] = pack2(v.x, v.y);
    }
}

__global__ void __launch_bounds__(256) conv_b(const float* __restrict__ W)
{
    unsigned i = blockIdx.x * 256 + threadIdx.x;
    int k = i >> 11, n = i & 2047;
    g_bh[(size_t)n * 512 + k] = __float2half_rn(W[i]);
}

// ---------------------------------------------------------------------------
// Kernel 1: x_proj GEMM — VERBATIM R10 (legacy fp16 mma, single B term,
// ldmatrix, 4-stage ring, occupancy 2).
// ---------------------------------------------------------------------------
#define GROW 80
#define GTILE (128 * GROW)
#define GSTAGE (2 * GTILE)
#define GHDR 1024
#define GSMEM (GHDR + 4 * GSTAGE)

__global__ void __launch_bounds__(256, 2) gemm_f16(const float* __restrict__ bias)
{
    extern __shared__ char smc[];
    const unsigned sm32 = smem_to_u32(smc);

    const int tid = threadIdx.x;
    const int n0  = blockIdx.x * 128;
    const int m0  = blockIdx.y * 128;
    const int warp = tid >> 5, lane = tid & 31;
    const int wm = warp & 1, wn = warp >> 1;
    const int r  = lane >> 2, cq = lane & 3;
    const int lr = lane & 15, lh = lane >> 4;

    float* sbias = (float*)smc;
    if (tid < 128) sbias[tid] = bias[n0 + tid];

    float acc[4][4][4];
#pragma unroll
    for (int i = 0; i < 4; i++)
#pragma unroll
        for (int j = 0; j < 4; j++)
#pragma unroll
            for (int k = 0; k < 4; k++) acc[i][j][k] = 0.f;

    auto issue = [&](int s) {
        char* base = smc + GHDR + (s & 3) * GSTAGE;
#pragma unroll
        for (int i = 0; i < 4; i++) {
            int idx  = tid + i * 256;
            int tile = idx >> 9;
            int q    = idx & 511;
            int row  = q >> 2, seg = q & 3;
            const __half* src =
                (tile == 0) ? g_ah + (size_t)(m0 + row) * 512 + s * 32 + seg * 8 :
                              g_bh + (size_t)(n0 + row) * 512 + s * 32 + seg * 8;
            cp16(base + tile * GTILE + row * GROW + seg * 16, src);
        }
        asm volatile("cp.async.commit_group;" ::: "memory");
    };

    issue(0);
    issue(1);
    issue(2);

    for (int s = 0; s < 16; s++) {
        if (s <= 13)      { asm volatile("cp.async.wait_group 2;" ::: "memory"); }
        else if (s == 14) { asm volatile("cp.async.wait_group 1;" ::: "memory"); }
        else              { asm volatile("cp.async.wait_group 0;" ::: "memory"); }
        __syncthreads();
        if (s + 3 < 16) issue(s + 3);

        const unsigned sb = sm32 + GHDR + (s & 3) * GSTAGE;
        const unsigned Aad = sb + (wm * 64 + lr) * GROW + lh * 16;
        const unsigned Bad = sb + GTILE + (wn * 32 + lr) * GROW + lh * 16;

#pragma unroll
        for (int kk = 0; kk < 2; kk++) {
            unsigned a[4][4];
#pragma unroll
            for (int mt = 0; mt < 4; mt++)
                ldmx4(a[mt], Aad + mt * 16 * GROW + kk * 32);

#pragma unroll
            for (int p = 0; p < 2; p++) {
                unsigned bq[4];
                ldmx4(bq, Bad + p * 16 * GROW + kk * 32);
#pragma unroll
                for (int mt = 0; mt < 4; mt++) {
                    mma16(acc[mt][2 * p],     a[mt][0], a[mt][1], a[mt][2], a[mt][3], bq[0], bq[2]);
                    mma16(acc[mt][2 * p + 1], a[mt][0], a[mt][1], a[mt][2], a[mt][3], bq[1], bq[3]);
                }
            }
        }
    }

    const int mbase = m0 + wm * 64;
    const int nbase = n0 + wn * 32;
#pragma unroll
    for (int nt = 0; nt < 4; nt++) {
        int nn = nbase + nt * 8 + cq * 2;
        float2 bb = *(const float2*)(sbias + nt * 8 + cq * 2 + wn * 32);
#pragma unroll
        for (int mt = 0; mt < 4; mt++) {
            int row0 = mbase + mt * 16 + r;
            int t0 = row0 & (T_ - 1), bi0 = row0 >> 10;
            float2 v0 = make_float2(acc[mt][nt][0] + bb.x, acc[mt][nt][1] + bb.y);
            *(float2*)&g_xproj[((size_t)(t0 * 64 + bi0) << 11) + nn] = v0;
            int row1 = row0 + 8;
            int t1 = row1 & (T_ - 1), bi1 = row1 >> 10;
            float2 v1 = make_float2(acc[mt][nt][2] + bb.x, acc[mt][nt][3] + bb.y);
            *(float2*)&g_xproj[((size_t)(t1 * 64 + bi1) << 11) + nn] = v1;
        }
    }
}

// ---------------------------------------------------------------------------
// Kernel 2: persistent LSTM recurrence — R5 structure, h stored fp16.
// ONLY storage-type change vs R5/R10 config: h global + smem chunks are
// halves (same [col][b] layout, same warp-local row-slab copies, halved
// cp.async count), A fragments load as LDS.u16 + half->float cvt, MMA stays
// tf32 2-term register Wh. Barrier, split-k, cell identical.
// ---------------------------------------------------------------------------
#define SHH_STRIDE 72                     // halves per 64-half row (+8 pad)
#define SHH_CHUNK (128 * SHH_STRIDE)      // halves per chunk
#define SG_STRIDE 18
#define SG_WARP  (64 * SG_STRIDE)

__global__ void __launch_bounds__(256, 1) lstm_kernel(
    const float* __restrict__ Wh,
    float* __restrict__ out)
{
    extern __shared__ char smraw[];
    __half* sh = (__half*)smraw;                              // 3*9216 halves = 55296 B
    float*  sg = (float*)(smraw + 3 * SHH_CHUNK * 2);         // 8*64*18 fl   = 36864 B
    float*  sx = (float*)(smraw + 3 * SHH_CHUNK * 2 + 8 * SG_WARP * 4); // 2*1024 fl

    const int tid = threadIdx.x;
    const int cta = blockIdx.x;
    const int warp = tid >> 5, lane = tid & 31;
    const int r = lane >> 2, cq = lane & 3;

    const unsigned base = ld_acq(&g_flags[cta * 32]);

    unsigned BH[16][2], BL[16][2];
#pragma unroll
    for (int c = 0; c < 4; c++)
#pragma unroll
        for (int j = 0; j < 2; j++) {
            int kt = c * 16 + j * 8 + warp;
            int k0 = kt << 3;
#pragma unroll
            for (int nt = 0; nt < 2; nt++) {
                int n = nt * 8 + r;
                int col = ((n >> 2) << 9) + (cta << 2) + (n & 3);
                float w0 = Wh[(size_t)(k0 + cq) * G4_ + col];
                float w1 = Wh[(size_t)(k0 + cq + 4) * G4_ + col];
                int bi = (c << 2) | (j << 1) | nt;
                BH[bi][0] = __float_as_uint(w0);
                BH[bi][1] = __float_as_uint(w1);
                BL[bi][0] = __float_as_uint(tf32_lo(w0));
                BL[bi][1] = __float_as_uint(tf32_lo(w1));
            }
        }

    // zero h buffer 0: 32768 halves = 16384 u32, 128 per CTA
    if (tid < 128) ((unsigned*)g_hbufh[0])[cta * 128 + tid] = 0u;

    {
        int b = tid >> 2, g = tid & 3;
        cp16(sx + b * 16 + g * 4,
             g_xproj + ((size_t)b << 11) + ((size_t)g << 9) + (cta << 2));
        asm volatile("cp.async.commit_group;" ::: "memory");
        asm volatile("cp.async.wait_group 0;" ::: "memory");
    }

    __syncthreads();
    {   // barrier 0: init complete
        unsigned tgt = base + 1;
        if (tid == 0) st_rel(&g_flags[cta * 32], tgt);
        if (tid < NCTA)
            while ((int)(ld_acq(&g_flags[tid * 32]) - tgt) < 0) {}
        __syncthreads();
    }

    const int eb = tid >> 2, ej = tid & 3;
    const int colj = (cta << 2) + ej;
    float c_reg = 0.f;

    // warp-local chunk copy: warp loads its own 16 rows (2x8) per chunk,
    // each row 64 halves = 128 B = 8 cp16 -> 2 cp16 per lane per j.
    auto issue_chunk = [&](const __half* hsrc, int ch) {
        const int buf = ch % 3;
#pragma unroll
        for (int j = 0; j < 2; j++) {
            const __half* s0 = hsrc + (size_t)(ch * 128 + j * 64 + warp * 8) * 64;
            __half* d0 = sh + buf * SHH_CHUNK + (j * 64 + warp * 8) * SHH_STRIDE;
#pragma unroll
            for (int i = 0; i < 2; i++) {
                int s_ = lane + 32 * i;            // 0..63
                int row8 = s_ >> 3, segc = s_ & 7;
                cp16(d0 + row8 * SHH_STRIDE + segc * 8, s0 + row8 * 64 + segc * 8);
            }
        }
    };

    for (int t = 0; t < T_; t++) {
        const __half* hsrc = g_hbufh[t & 1];

        issue_chunk(hsrc, 0);
        asm volatile("cp.async.commit_group;" ::: "memory");
        issue_chunk(hsrc, 1);
        asm volatile("cp.async.commit_group;" ::: "memory");

        float acc[4][2][4];
#pragma unroll
        for (int mt = 0; mt < 4; mt++)
#pragma unroll
            for (int nt = 0; nt < 2; nt++)
#pragma unroll
                for (int k = 0; k < 4; k++) acc[mt][nt][k] = 0.f;

#pragma unroll
        for (int ch = 0; ch < 4; ch++) {
            if (ch < 3) { asm volatile("cp.async.wait_group 1;" ::: "memory"); }
            else        { asm volatile("cp.async.wait_group 0;" ::: "memory"); }
            __syncwarp();

            if (ch == 0) {
                issue_chunk(hsrc, 2);
                if (t + 1 < T_) {
                    int b = tid >> 2, g = tid & 3;
                    cp16(sx + ((t + 1) & 1) * 1024 + b * 16 + g * 4,
                         g_xproj + ((size_t)((t + 1) * 64 + b) << 11)
                                 + ((size_t)g << 9) + (cta << 2));
                }
                asm volatile("cp.async.commit_group;" ::: "memory");
            } else if (ch == 1) {
                issue_chunk(hsrc, 3);
                asm volatile("cp.async.commit_group;" ::: "memory");
            }

            const __half* hb = sh + (ch % 3) * SHH_CHUNK;
#pragma unroll
            for (int j = 0; j < 2; j++) {
                const int lk0 = ((j << 3) + warp) << 3;
                unsigned a[4][4];
#pragma unroll
                for (int mt = 0; mt < 4; mt++) {
                    const __half* ap = hb + (lk0 + cq) * SHH_STRIDE + mt * 16 + r;
                    a[mt][0] = __float_as_uint(__half2float(ap[0]));
                    a[mt][1] = __float_as_uint(__half2float(ap[8]));
                    a[mt][2] = __float_as_uint(__half2float(ap[4 * SHH_STRIDE]));
                    a[mt][3] = __float_as_uint(__half2float(ap[4 * SHH_STRIDE + 8]));
                }
                const int bi0 = (ch << 2) | (j << 1);
#pragma unroll
                for (int nt = 0; nt < 2; nt++)
#pragma unroll
                    for (int mt = 0; mt < 4; mt++)
                        mma8(acc[mt][nt], a[mt][0], a[mt][1], a[mt][2], a[mt][3],
                             BH[bi0 | nt][0], BH[bi0 | nt][1]);
#pragma unroll
                for (int nt = 0; nt < 2; nt++)
#pragma unroll
                    for (int mt = 0; mt < 4; mt++)
                        mma8(acc[mt][nt], a[mt][0], a[mt][1], a[mt][2], a[mt][3],
                             BL[bi0 | nt][0], BL[bi0 | nt][1]);
            }
        }

        {
            float* sgp = sg + warp * SG_WARP;
#pragma unroll
            for (int mt = 0; mt < 4; mt++) {
                int b0 = mt * 16 + r;
#pragma unroll
                for (int nt = 0; nt < 2; nt++) {
                    int n = nt * 8 + cq * 2;
                    *(float2*)&sgp[b0 * SG_STRIDE + n] =
                        make_float2(acc[mt][nt][0], acc[mt][nt][1]);
                    *(float2*)&sgp[(b0 + 8) * SG_STRIDE + n] =
                        make_float2(acc[mt][nt][2], acc[mt][nt][3]);
                }
            }
        }
        __syncthreads();

        {
            const float* sxb = sx + (t & 1) * 1024;
            float v[4];
#pragma unroll
            for (int g = 0; g < 4; g++) {
                int n = (g << 2) + ej;
                float s = sxb[eb * 16 + n];
#pragma unroll
                for (int w = 0; w < 8; w++) s += sg[w * SG_WARP + eb * SG_STRIDE + n];
                v[g] = s;
            }
            float si = 1.f / (1.f + __expf(-v[0]));
            float sf = 1.f / (1.f + __expf(-v[1]));
            float tg = tanhf(v[2]);
            float so = 1.f / (1.f + __expf(-v[3]));
            c_reg = sf * c_reg + si * tg;
            float hn = so * tanhf(c_reg);

            g_hbufh[(t + 1) & 1][(colj << 6) + eb] = __float2half_rn(hn);

            if (t == T_ - 1) {
                out[eb * H_ + colj]           = c_reg;   // c_fin
                out[B_ * H_ + eb * H_ + colj] = hn;      // h_fin
            }
        }

        __syncthreads();
        {
            unsigned tgt = base + 2 + (unsigned)t;
            if (tid == 0) st_rel(&g_flags[cta * 32], tgt);
            if (tid < NCTA)
                while ((int)(ld_acq(&g_flags[tid * 32]) - tgt) < 0) {}
            __syncthreads();
        }
    }
}

// ---------------------------------------------------------------------------
extern "C" void kernel_launch(void* const* d_in, const int* in_sizes, int n_in,
                              void* d_out, int out_size)
{
    const float* inputs = (const float*)d_in[0];  // [B, T, F]
    const float* Wx     = (const float*)d_in[1];  // [F, 4H]
    const float* Wh     = (const float*)d_in[2];  // [H, 4H]
    const float* bias   = (const float*)d_in[3];  // [4H]
    float* out = (float*)d_out;                   // [2, B, H] = (c_fin, h_fin)

    (void)in_sizes; (void)n_in; (void)out_size;

    conv_a<<<8192, 256>>>(inputs);
    conv_b<<<4096, 256>>>(Wx);

    cudaFuncSetAttribute(gemm_f16, cudaFuncAttributeMaxDynamicSharedMemorySize, GSMEM);
    gemm_f16<<<dim3(G4_ / 128, (B_ * T_) / 128), 256, GSMEM>>>(bias);

    const int lstm_smem = 3 * SHH_CHUNK * 2 + 8 * SG_WARP * 4 + 2 * 1024 * 4; // 100352 B
    cudaFuncSetAttribute(lstm_kernel, cudaFuncAttributeMaxDynamicSharedMemorySize, lstm_smem);
    lstm_kernel<<<NCTA, 256, lstm_smem>>>(Wh, out);
}

// round 12
// speedup vs baseline: 1.0204x; 1.0204x over previous
#include <cuda_runtime.h>
#include <cuda_fp16.h>
#include <cstdint>
#include <cstddef>

#define B_  64
#define T_  1024
#define F_  512
#define H_  512
#define G4_ 2048   // 4H
#define NCTA 128

__device__ float  g_xproj[(size_t)T_ * B_ * G4_];        // [t][b][col] fp32
__device__ __half g_hbufh[2][H_ * B_];                   // [col(k)][b] fp16, double-buffered
__device__ unsigned g_flags[NCTA * 32];                  // 1 flag per 128B line
__device__ __half g_ah[(size_t)B_ * T_ * F_];            // inputs as fp16 [m][k]
__device__ __half g_bh[(size_t)G4_ * F_];                // Wx^T fp16 [n][k]

// ---------------------------------------------------------------------------
// helpers
// ---------------------------------------------------------------------------
__device__ __forceinline__ void cp16(void* dst, const void* src)
{
    unsigned d = (unsigned)__cvta_generic_to_shared(dst);
    asm volatile("cp.async.cg.shared.global [%0], [%1], 16;" :: "r"(d), "l"(src) : "memory");
}

__device__ __forceinline__ unsigned ld_acq(const unsigned* p)
{
    unsigned v;
    asm volatile("ld.acquire.gpu.global.u32 %0, [%1];" : "=r"(v) : "l"(p) : "memory");
    return v;
}

__device__ __forceinline__ void st_rel(unsigned* p, unsigned v)
{
    asm volatile("st.release.gpu.global.u32 [%0], %1;" :: "l"(p), "r"(v) : "memory");
}

__device__ __forceinline__ unsigned pack2(float a, float b)
{
    __half2 h = __floats2half2_rn(a, b);
    return *(unsigned*)&h;
}

// lo part of the tf32 split: x - truncate_to_tf32(x)  (exact in fp32)
__device__ __forceinline__ float tf32_lo(float x)
{
    unsigned u = __float_as_uint(x) & 0xFFFFE000u;
    return x - __uint_as_float(u);
}

__device__ __forceinline__ void mma8(float* c,
    unsigned a0, unsigned a1, unsigned a2, unsigned a3,
    unsigned b0, unsigned b1)
{
    asm volatile(
        "mma.sync.aligned.m16n8k8.row.col.f32.tf32.tf32.f32 "
        "{%0,%1,%2,%3}, {%4,%5,%6,%7}, {%8,%9}, {%0,%1,%2,%3};"
        : "+f"(c[0]), "+f"(c[1]), "+f"(c[2]), "+f"(c[3])
        : "r"(a0), "r"(a1), "r"(a2), "r"(a3), "r"(b0), "r"(b1));
}

__device__ __forceinline__ void mma16(float* c,
    unsigned a0, unsigned a1, unsigned a2, unsigned a3,
    unsigned b0, unsigned b1)
{
    asm volatile(
        "mma.sync.aligned.m16n8k16.row.col.f32.f16.f16.f32 "
        "{%0,%1,%2,%3}, {%4,%5,%6,%7}, {%8,%9}, {%0,%1,%2,%3};"
        : "+f"(c[0]), "+f"(c[1]), "+f"(c[2]), "+f"(c[3])
        : "r"(a0), "r"(a1), "r"(a2), "r"(a3), "r"(b0), "r"(b1));
}

__device__ __forceinline__ void ldmx4(unsigned* r, unsigned addr)
{
    asm volatile(
        "ldmatrix.sync.aligned.m8n8.x4.shared.b16 {%0,%1,%2,%3}, [%4];"
        : "=r"(r[0]), "=r"(r[1]), "=r"(r[2]), "=r"(r[3]) : "r"(addr));
}

__device__ __forceinline__ uint32_t smem_to_u32(const void* p) {
    uint32_t a;
    asm("{ .reg .u64 t; cvta.to.shared.u64 t, %1; cvt.u32.u64 %0, t; }"
        : "=r"(a) : "l"(p));
    return a;
}

// ---------------------------------------------------------------------------
// Prep kernels: inputs -> fp16 [m][k]; Wx -> transposed fp16 [n][k]
// ---------------------------------------------------------------------------
__global__ void __launch_bounds__(256) conv_a(const float* __restrict__ A)
{
    unsigned i0 = blockIdx.x * 256 + threadIdx.x;
#pragma unroll
    for (int j = 0; j < 8; j++) {
        unsigned i = i0 + j * (8192u * 256u);
        float2 v = ((const float2*)A)[i];
        ((unsigned*)g_ah)[i] = pack2(v.x, v.y);
    }
}

__global__ void __launch_bounds__(256) conv_b(const float* __restrict__ W)
{
    unsigned i = blockIdx.x * 256 + threadIdx.x;
    int k = i >> 11, n = i & 2047;
    g_bh[(size_t)n * 512 + k] = __float2half_rn(W[i]);
}

// ---------------------------------------------------------------------------
// Kernel 1: x_proj GEMM — VERBATIM R10 (legacy fp16 mma, single B term,
// ldmatrix, 4-stage ring, occupancy 2).
// ---------------------------------------------------------------------------
#define GROW 80
#define GTILE (128 * GROW)
#define GSTAGE (2 * GTILE)
#define GHDR 1024
#define GSMEM (GHDR + 4 * GSTAGE)

__global__ void __launch_bounds__(256, 2) gemm_f16(const float* __restrict__ bias)
{
    extern __shared__ char smc[];
    const unsigned sm32 = smem_to_u32(smc);

    const int tid = threadIdx.x;
    const int n0  = blockIdx.x * 128;
    const int m0  = blockIdx.y * 128;
    const int warp = tid >> 5, lane = tid & 31;
    const int wm = warp & 1, wn = warp >> 1;
    const int r  = lane >> 2, cq = lane & 3;
    const int lr = lane & 15, lh = lane >> 4;

    float* sbias = (float*)smc;
    if (tid < 128) sbias[tid] = bias[n0 + tid];

    float acc[4][4][4];
#pragma unroll
    for (int i = 0; i < 4; i++)
#pragma unroll
        for (int j = 0; j < 4; j++)
#pragma unroll
            for (int k = 0; k < 4; k++) acc[i][j][k] = 0.f;

    auto issue = [&](int s) {
        char* base = smc + GHDR + (s & 3) * GSTAGE;
#pragma unroll
        for (int i = 0; i < 4; i++) {
            int idx  = tid + i * 256;
            int tile = idx >> 9;
            int q    = idx & 511;
            int row  = q >> 2, seg = q & 3;
            const __half* src =
                (tile == 0) ? g_ah + (size_t)(m0 + row) * 512 + s * 32 + seg * 8 :
                              g_bh + (size_t)(n0 + row) * 512 + s * 32 + seg * 8;
            cp16(base + tile * GTILE + row * GROW + seg * 16, src);
        }
        asm volatile("cp.async.commit_group;" ::: "memory");
    };

    issue(0);
    issue(1);
    issue(2);

    for (int s = 0; s < 16; s++) {
        if (s <= 13)      { asm volatile("cp.async.wait_group 2;" ::: "memory"); }
        else if (s == 14) { asm volatile("cp.async.wait_group 1;" ::: "memory"); }
        else              { asm volatile("cp.async.wait_group 0;" ::: "memory"); }
        __syncthreads();
        if (s + 3 < 16) issue(s + 3);

        const unsigned sb = sm32 + GHDR + (s & 3) * GSTAGE;
        const unsigned Aad = sb + (wm * 64 + lr) * GROW + lh * 16;
        const unsigned Bad = sb + GTILE + (wn * 32 + lr) * GROW + lh * 16;

#pragma unroll
        for (int kk = 0; kk < 2; kk++) {
            unsigned a[4][4];
#pragma unroll
            for (int mt = 0; mt < 4; mt++)
                ldmx4(a[mt], Aad + mt * 16 * GROW + kk * 32);

#pragma unroll
            for (int p = 0; p < 2; p++) {
                unsigned bq[4];
                ldmx4(bq, Bad + p * 16 * GROW + kk * 32);
#pragma unroll
                for (int mt = 0; mt < 4; mt++) {
                    mma16(acc[mt][2 * p],     a[mt][0], a[mt][1], a[mt][2], a[mt][3], bq[0], bq[2]);
                    mma16(acc[mt][2 * p + 1], a[mt][0], a[mt][1], a[mt][2], a[mt][3], bq[1], bq[3]);
                }
            }
        }
    }

    const int mbase = m0 + wm * 64;
    const int nbase = n0 + wn * 32;
#pragma unroll
    for (int nt = 0; nt < 4; nt++) {
        int nn = nbase + nt * 8 + cq * 2;
        float2 bb = *(const float2*)(sbias + nt * 8 + cq * 2 + wn * 32);
#pragma unroll
        for (int mt = 0; mt < 4; mt++) {
            int row0 = mbase + mt * 16 + r;
            int t0 = row0 & (T_ - 1), bi0 = row0 >> 10;
            float2 v0 = make_float2(acc[mt][nt][0] + bb.x, acc[mt][nt][1] + bb.y);
            *(float2*)&g_xproj[((size_t)(t0 * 64 + bi0) << 11) + nn] = v0;
            int row1 = row0 + 8;
            int t1 = row1 & (T_ - 1), bi1 = row1 >> 10;
            float2 v1 = make_float2(acc[mt][nt][2] + bb.x, acc[mt][nt][3] + bb.y);
            *(float2*)&g_xproj[((size_t)(t1 * 64 + bi1) << 11) + nn] = v1;
        }
    }
}

// ---------------------------------------------------------------------------
// Kernel 2: persistent LSTM recurrence — R11 datapath (fp16 h [col][b],
// tf32 2-term register Wh). NEW step schedule:
//   - all 4 h-chunks issued up front as groups 0..3 into 4 DEDICATED buffers
//     (no ring; cross-step reuse ordered by the grid barrier),
//   - x_proj(t+1) prefetch is its OWN group 4, issued at step start and never
//     waited inside the step (full step to cover DRAM latency),
//   - per-chunk waits: wait_group 4,3,2,1 -> each MMA waits only on its chunk.
// ---------------------------------------------------------------------------
#define SHH_STRIDE 72                     // halves per 64-half row (+8 pad)
#define SHH_CHUNK (128 * SHH_STRIDE)      // halves per chunk
#define SG_STRIDE 18
#define SG_WARP  (64 * SG_STRIDE)

__global__ void __launch_bounds__(256, 1) lstm_kernel(
    const float* __restrict__ Wh,
    float* __restrict__ out)
{
    extern __shared__ char smraw[];
    __half* sh = (__half*)smraw;                              // 4*9216 halves = 73728 B
    float*  sg = (float*)(smraw + 4 * SHH_CHUNK * 2);         // 8*64*18 fl   = 36864 B
    float*  sx = (float*)(smraw + 4 * SHH_CHUNK * 2 + 8 * SG_WARP * 4); // 2*1024 fl

    const int tid = threadIdx.x;
    const int cta = blockIdx.x;
    const int warp = tid >> 5, lane = tid & 31;
    const int r = lane >> 2, cq = lane & 3;

    const unsigned base = ld_acq(&g_flags[cta * 32]);

    unsigned BH[16][2], BL[16][2];
#pragma unroll
    for (int c = 0; c < 4; c++)
#pragma unroll
        for (int j = 0; j < 2; j++) {
            int kt = c * 16 + j * 8 + warp;
            int k0 = kt << 3;
#pragma unroll
            for (int nt = 0; nt < 2; nt++) {
                int n = nt * 8 + r;
                int col = ((n >> 2) << 9) + (cta << 2) + (n & 3);
                float w0 = Wh[(size_t)(k0 + cq) * G4_ + col];
                float w1 = Wh[(size_t)(k0 + cq + 4) * G4_ + col];
                int bi = (c << 2) | (j << 1) | nt;
                BH[bi][0] = __float_as_uint(w0);
                BH[bi][1] = __float_as_uint(w1);
                BL[bi][0] = __float_as_uint(tf32_lo(w0));
                BL[bi][1] = __float_as_uint(tf32_lo(w1));
            }
        }

    // zero h buffer 0: 32768 halves = 16384 u32, 128 per CTA
    if (tid < 128) ((unsigned*)g_hbufh[0])[cta * 128 + tid] = 0u;

    {   // load x_proj(t=0) into sx[0]
        int b = tid >> 2, g = tid & 3;
        cp16(sx + b * 16 + g * 4,
             g_xproj + ((size_t)b << 11) + ((size_t)g << 9) + (cta << 2));
        asm volatile("cp.async.commit_group;" ::: "memory");
        asm volatile("cp.async.wait_group 0;" ::: "memory");
    }

    __syncthreads();
    {   // barrier 0: init complete
        unsigned tgt = base + 1;
        if (tid == 0) st_rel(&g_flags[cta * 32], tgt);
        if (tid < NCTA)
            while ((int)(ld_acq(&g_flags[tid * 32]) - tgt) < 0) {}
        __syncthreads();
    }

    const int eb = tid >> 2, ej = tid & 3;
    const int colj = (cta << 2) + ej;
    float c_reg = 0.f;

    // warp-local chunk copy into DEDICATED buffer ch.
    auto issue_chunk = [&](const __half* hsrc, int ch) {
#pragma unroll
        for (int j = 0; j < 2; j++) {
            const __half* s0 = hsrc + (size_t)(ch * 128 + j * 64 + warp * 8) * 64;
            __half* d0 = sh + ch * SHH_CHUNK + (j * 64 + warp * 8) * SHH_STRIDE;
#pragma unroll
            for (int i = 0; i < 2; i++) {
                int s_ = lane + 32 * i;            // 0..63
                int row8 = s_ >> 3, segc = s_ & 7;
                cp16(d0 + row8 * SHH_STRIDE + segc * 8, s0 + row8 * 64 + segc * 8);
            }
        }
        asm volatile("cp.async.commit_group;" ::: "memory");
    };

    for (int t = 0; t < T_; t++) {
        const __half* hsrc = g_hbufh[t & 1];

        // groups 0..3: h chunks; group 4: x_proj(t+1) prefetch (never waited
        // inside this step -> full step to cover DRAM latency)
        issue_chunk(hsrc, 0);
        issue_chunk(hsrc, 1);
        issue_chunk(hsrc, 2);
        issue_chunk(hsrc, 3);
        if (t + 1 < T_) {
            int b = tid >> 2, g = tid & 3;
            cp16(sx + ((t + 1) & 1) * 1024 + b * 16 + g * 4,
                 g_xproj + ((size_t)((t + 1) * 64 + b) << 11)
                         + ((size_t)g << 9) + (cta << 2));
        }
        asm volatile("cp.async.commit_group;" ::: "memory");

        float acc[4][2][4];
#pragma unroll
        for (int mt = 0; mt < 4; mt++)
#pragma unroll
            for (int nt = 0; nt < 2; nt++)
#pragma unroll
                for (int k = 0; k < 4; k++) acc[mt][nt][k] = 0.f;

#pragma unroll
        for (int ch = 0; ch < 4; ch++) {
            switch (ch) {   // wait only for this chunk's group (FIFO order)
                case 0: asm volatile("cp.async.wait_group 4;" ::: "memory"); break;
                case 1: asm volatile("cp.async.wait_group 3;" ::: "memory"); break;
                case 2: asm volatile("cp.async.wait_group 2;" ::: "memory"); break;
                default: asm volatile("cp.async.wait_group 1;" ::: "memory"); break;
            }
            __syncwarp();

            const __half* hb = sh + ch * SHH_CHUNK;
#pragma unroll
            for (int j = 0; j < 2; j++) {
                const int lk0 = ((j << 3) + warp) << 3;
                unsigned a[4][4];
#pragma unroll
                for (int mt = 0; mt < 4; mt++) {
                    const __half* ap = hb + (lk0 + cq) * SHH_STRIDE + mt * 16 + r;
                    a[mt][0] = __float_as_uint(__half2float(ap[0]));
                    a[mt][1] = __float_as_uint(__half2float(ap[8]));
                    a[mt][2] = __float_as_uint(__half2float(ap[4 * SHH_STRIDE]));
                    a[mt][3] = __float_as_uint(__half2float(ap[4 * SHH_STRIDE + 8]));
                }
                const int bi0 = (ch << 2) | (j << 1);
#pragma unroll
                for (int nt = 0; nt < 2; nt++)
#pragma unroll
                    for (int mt = 0; mt < 4; mt++)
                        mma8(acc[mt][nt], a[mt][0], a[mt][1], a[mt][2], a[mt][3],
                             BH[bi0 | nt][0], BH[bi0 | nt][1]);
#pragma unroll
                for (int nt = 0; nt < 2; nt++)
#pragma unroll
                    for (int mt = 0; mt < 4; mt++)
                        mma8(acc[mt][nt], a[mt][0], a[mt][1], a[mt][2], a[mt][3],
                             BL[bi0 | nt][0], BL[bi0 | nt][1]);
            }
        }

        {
            float* sgp = sg + warp * SG_WARP;
#pragma unroll
            for (int mt = 0; mt < 4; mt++) {
                int b0 = mt * 16 + r;
#pragma unroll
                for (int nt = 0; nt < 2; nt++) {
                    int n = nt * 8 + cq * 2;
                    *(float2*)&sgp[b0 * SG_STRIDE + n] =
                        make_float2(acc[mt][nt][0], acc[mt][nt][1]);
                    *(float2*)&sgp[(b0 + 8) * SG_STRIDE + n] =
                        make_float2(acc[mt][nt][2], acc[mt][nt][3]);
                }
            }
        }
        __syncthreads();

        {
            const float* sxb = sx + (t & 1) * 1024;
            float v[4];
#pragma unroll
            for (int g = 0; g < 4; g++) {
                int n = (g << 2) + ej;
                float s = sxb[eb * 16 + n];
#pragma unroll
                for (int w = 0; w < 8; w++) s += sg[w * SG_WARP + eb * SG_STRIDE + n];
                v[g] = s;
            }
            float si = 1.f / (1.f + __expf(-v[0]));
            float sf = 1.f / (1.f + __expf(-v[1]));
            float tg = tanhf(v[2]);
            float so = 1.f / (1.f + __expf(-v[3]));
            c_reg = sf * c_reg + si * tg;
            float hn = so * tanhf(c_reg);

            g_hbufh[(t + 1) & 1][(colj << 6) + eb] = __float2half_rn(hn);

            if (t == T_ - 1) {
                out[eb * H_ + colj]           = c_reg;   // c_fin
                out[B_ * H_ + eb * H_ + colj] = hn;      // h_fin
            }
        }

        __syncthreads();
        {
            unsigned tgt = base + 2 + (unsigned)t;
            if (tid == 0) st_rel(&g_flags[cta * 32], tgt);
            if (tid < NCTA)
                while ((int)(ld_acq(&g_flags[tid * 32]) - tgt) < 0) {}
            __syncthreads();
        }
    }
}

// ---------------------------------------------------------------------------
extern "C" void kernel_launch(void* const* d_in, const int* in_sizes, int n_in,
                              void* d_out, int out_size)
{
    const float* inputs = (const float*)d_in[0];  // [B, T, F]
    const float* Wx     = (const float*)d_in[1];  // [F, 4H]
    const float* Wh     = (const float*)d_in[2];  // [H, 4H]
    const float* bias   = (const float*)d_in[3];  // [4H]
    float* out = (float*)d_out;                   // [2, B, H] = (c_fin, h_fin)

    (void)in_sizes; (void)n_in; (void)out_size;

    conv_a<<<8192, 256>>>(inputs);
    conv_b<<<4096, 256>>>(Wx);

    cudaFuncSetAttribute(gemm_f16, cudaFuncAttributeMaxDynamicSharedMemorySize, GSMEM);
    gemm_f16<<<dim3(G4_ / 128, (B_ * T_) / 128), 256, GSMEM>>>(bias);

    const int lstm_smem = 4 * SHH_CHUNK * 2 + 8 * SG_WARP * 4 + 2 * 1024 * 4; // 118784 B
    cudaFuncSetAttribute(lstm_kernel, cudaFuncAttributeMaxDynamicSharedMemorySize, lstm_smem);
    lstm_kernel<<<NCTA, 256, lstm_smem>>>(Wh, out);
}

// round 13
// speedup vs baseline: 1.1282x; 1.1056x over previous
#include <cuda_runtime.h>
#include <cuda_fp16.h>
#include <cstdint>
#include <cstddef>

#define B_  64
#define T_  1024
#define F_  512
#define H_  512
#define G4_ 2048   // 4H
#define NCTA 128

__device__ float  g_xproj[(size_t)T_ * B_ * G4_];        // [t][b][col] fp32
__device__ __half g_hbufh[2][H_ * B_];                   // [col(k)][b] fp16, double-buffered
__device__ unsigned g_flags[NCTA * 32];                  // 1 flag per 128B line
__device__ __half g_ah[(size_t)B_ * T_ * F_];            // inputs as fp16 [m][k]
__device__ __half g_bh[(size_t)G4_ * F_];                // Wx^T fp16 [n][k]

// ---------------------------------------------------------------------------
// helpers
// ---------------------------------------------------------------------------
__device__ __forceinline__ void cp16(void* dst, const void* src)
{
    unsigned d = (unsigned)__cvta_generic_to_shared(dst);
    asm volatile("cp.async.cg.shared.global [%0], [%1], 16;" :: "r"(d), "l"(src) : "memory");
}

__device__ __forceinline__ unsigned ld_acq(const unsigned* p)
{
    unsigned v;
    asm volatile("ld.acquire.gpu.global.u32 %0, [%1];" : "=r"(v) : "l"(p) : "memory");
    return v;
}

__device__ __forceinline__ void st_rel(unsigned* p, unsigned v)
{
    asm volatile("st.release.gpu.global.u32 [%0], %1;" :: "l"(p), "r"(v) : "memory");
}

__device__ __forceinline__ unsigned pack2(float a, float b)
{
    __half2 h = __floats2half2_rn(a, b);
    return *(unsigned*)&h;
}

__device__ __forceinline__ void mma8(float* c,
    unsigned a0, unsigned a1, unsigned a2, unsigned a3,
    unsigned b0, unsigned b1)
{
    asm volatile(
        "mma.sync.aligned.m16n8k8.row.col.f32.tf32.tf32.f32 "
        "{%0,%1,%2,%3}, {%4,%5,%6,%7}, {%8,%9}, {%0,%1,%2,%3};"
        : "+f"(c[0]), "+f"(c[1]), "+f"(c[2]), "+f"(c[3])
        : "r"(a0), "r"(a1), "r"(a2), "r"(a3), "r"(b0), "r"(b1));
}

__device__ __forceinline__ void mma16(float* c,
    unsigned a0, unsigned a1, unsigned a2, unsigned a3,
    unsigned b0, unsigned b1)
{
    asm volatile(
        "mma.sync.aligned.m16n8k16.row.col.f32.f16.f16.f32 "
        "{%0,%1,%2,%3}, {%4,%5,%6,%7}, {%8,%9}, {%0,%1,%2,%3};"
        : "+f"(c[0]), "+f"(c[1]), "+f"(c[2]), "+f"(c[3])
        : "r"(a0), "r"(a1), "r"(a2), "r"(a3), "r"(b0), "r"(b1));
}

__device__ __forceinline__ void ldmx4(unsigned* r, unsigned addr)
{
    asm volatile(
        "ldmatrix.sync.aligned.m8n8.x4.shared.b16 {%0,%1,%2,%3}, [%4];"
        : "=r"(r[0]), "=r"(r[1]), "=r"(r[2]), "=r"(r[3]) : "r"(addr));
}

__device__ __forceinline__ uint32_t smem_to_u32(const void* p) {
    uint32_t a;
    asm("{ .reg .u64 t; cvta.to.shared.u64 t, %1; cvt.u32.u64 %0, t; }"
        : "=r"(a) : "l"(p));
    return a;
}

// ---------------------------------------------------------------------------
// Prep kernels: inputs -> fp16 [m][k]; Wx -> transposed fp16 [n][k]
// ---------------------------------------------------------------------------
__global__ void __launch_bounds__(256) conv_a(const float* __restrict__ A)
{
    unsigned i0 = blockIdx.x * 256 + threadIdx.x;
#pragma unroll
    for (int j = 0; j < 8; j++) {
        unsigned i = i0 + j * (8192u * 256u);
        float2 v = ((const float2*)A)[i];
        ((unsigned*)g_ah)[i] = pack2(v.x, v.y);
    }
}

__global__ void __launch_bounds__(256) conv_b(const float* __restrict__ W)
{
    unsigned i = blockIdx.x * 256 + threadIdx.x;
    int k = i >> 11, n = i & 2047;
    g_bh[(size_t)n * 512 + k] = __float2half_rn(W[i]);
}

// ---------------------------------------------------------------------------
// Kernel 1: x_proj GEMM — VERBATIM R10 (legacy fp16 mma, single B term,
// ldmatrix, 4-stage ring, occupancy 2).
// ---------------------------------------------------------------------------
#define GROW 80
#define GTILE (128 * GROW)
#define GSTAGE (2 * GTILE)
#define GHDR 1024
#define GSMEM (GHDR + 4 * GSTAGE)

__global__ void __launch_bounds__(256, 2) gemm_f16(const float* __restrict__ bias)
{
    extern __shared__ char smc[];
    const unsigned sm32 = smem_to_u32(smc);

    const int tid = threadIdx.x;
    const int n0  = blockIdx.x * 128;
    const int m0  = blockIdx.y * 128;
    const int warp = tid >> 5, lane = tid & 31;
    const int wm = warp & 1, wn = warp >> 1;
    const int r  = lane >> 2, cq = lane & 3;
    const int lr = lane & 15, lh = lane >> 4;

    float* sbias = (float*)smc;
    if (tid < 128) sbias[tid] = bias[n0 + tid];

    float acc[4][4][4];
#pragma unroll
    for (int i = 0; i < 4; i++)
#pragma unroll
        for (int j = 0; j < 4; j++)
#pragma unroll
            for (int k = 0; k < 4; k++) acc[i][j][k] = 0.f;

    auto issue = [&](int s) {
        char* base = smc + GHDR + (s & 3) * GSTAGE;
#pragma unroll
        for (int i = 0; i < 4; i++) {
            int idx  = tid + i * 256;
            int tile = idx >> 9;
            int q    = idx & 511;
            int row  = q >> 2, seg = q & 3;
            const __half* src =
                (tile == 0) ? g_ah + (size_t)(m0 + row) * 512 + s * 32 + seg * 8 :
                              g_bh + (size_t)(n0 + row) * 512 + s * 32 + seg * 8;
            cp16(base + tile * GTILE + row * GROW + seg * 16, src);
        }
        asm volatile("cp.async.commit_group;" ::: "memory");
    };

    issue(0);
    issue(1);
    issue(2);

    for (int s = 0; s < 16; s++) {
        if (s <= 13)      { asm volatile("cp.async.wait_group 2;" ::: "memory"); }
        else if (s == 14) { asm volatile("cp.async.wait_group 1;" ::: "memory"); }
        else              { asm volatile("cp.async.wait_group 0;" ::: "memory"); }
        __syncthreads();
        if (s + 3 < 16) issue(s + 3);

        const unsigned sb = sm32 + GHDR + (s & 3) * GSTAGE;
        const unsigned Aad = sb + (wm * 64 + lr) * GROW + lh * 16;
        const unsigned Bad = sb + GTILE + (wn * 32 + lr) * GROW + lh * 16;

#pragma unroll
        for (int kk = 0; kk < 2; kk++) {
            unsigned a[4][4];
#pragma unroll
            for (int mt = 0; mt < 4; mt++)
                ldmx4(a[mt], Aad + mt * 16 * GROW + kk * 32);

#pragma unroll
            for (int p = 0; p < 2; p++) {
                unsigned bq[4];
                ldmx4(bq, Bad + p * 16 * GROW + kk * 32);
#pragma unroll
                for (int mt = 0; mt < 4; mt++) {
                    mma16(acc[mt][2 * p],     a[mt][0], a[mt][1], a[mt][2], a[mt][3], bq[0], bq[2]);
                    mma16(acc[mt][2 * p + 1], a[mt][0], a[mt][1], a[mt][2], a[mt][3], bq[1], bq[3]);
                }
            }
        }
    }

    const int mbase = m0 + wm * 64;
    const int nbase = n0 + wn * 32;
#pragma unroll
    for (int nt = 0; nt < 4; nt++) {
        int nn = nbase + nt * 8 + cq * 2;
        float2 bb = *(const float2*)(sbias + nt * 8 + cq * 2 + wn * 32);
#pragma unroll
        for (int mt = 0; mt < 4; mt++) {
            int row0 = mbase + mt * 16 + r;
            int t0 = row0 & (T_ - 1), bi0 = row0 >> 10;
            float2 v0 = make_float2(acc[mt][nt][0] + bb.x, acc[mt][nt][1] + bb.y);
            *(float2*)&g_xproj[((size_t)(t0 * 64 + bi0) << 11) + nn] = v0;
            int row1 = row0 + 8;
            int t1 = row1 & (T_ - 1), bi1 = row1 >> 10;
            float2 v1 = make_float2(acc[mt][nt][2] + bb.x, acc[mt][nt][3] + bb.y);
            *(float2*)&g_xproj[((size_t)(t1 * 64 + bi1) << 11) + nn] = v1;
        }
    }
}

// ---------------------------------------------------------------------------
// Kernel 2: persistent LSTM recurrence — R12 structure; SINGLE-TERM Wh
// (tf32 hi only; lo term + BL regs deleted -> 32 mma8/chunk instead of 64).
// h fp16 [col][b]; 4 dedicated chunk buffers, up-front groups, x_proj own
// group never waited in-step; release/acquire grid barrier.
// ---------------------------------------------------------------------------
#define SHH_STRIDE 72                     // halves per 64-half row (+8 pad)
#define SHH_CHUNK (128 * SHH_STRIDE)      // halves per chunk
#define SG_STRIDE 18
#define SG_WARP  (64 * SG_STRIDE)

__global__ void __launch_bounds__(256, 1) lstm_kernel(
    const float* __restrict__ Wh,
    float* __restrict__ out)
{
    extern __shared__ char smraw[];
    __half* sh = (__half*)smraw;                              // 4*9216 halves = 73728 B
    float*  sg = (float*)(smraw + 4 * SHH_CHUNK * 2);         // 8*64*18 fl   = 36864 B
    float*  sx = (float*)(smraw + 4 * SHH_CHUNK * 2 + 8 * SG_WARP * 4); // 2*1024 fl

    const int tid = threadIdx.x;
    const int cta = blockIdx.x;
    const int warp = tid >> 5, lane = tid & 31;
    const int r = lane >> 2, cq = lane & 3;

    const unsigned base = ld_acq(&g_flags[cta * 32]);

    unsigned BH[16][2];
#pragma unroll
    for (int c = 0; c < 4; c++)
#pragma unroll
        for (int j = 0; j < 2; j++) {
            int kt = c * 16 + j * 8 + warp;
            int k0 = kt << 3;
#pragma unroll
            for (int nt = 0; nt < 2; nt++) {
                int n = nt * 8 + r;
                int col = ((n >> 2) << 9) + (cta << 2) + (n & 3);
                float w0 = Wh[(size_t)(k0 + cq) * G4_ + col];
                float w1 = Wh[(size_t)(k0 + cq + 4) * G4_ + col];
                int bi = (c << 2) | (j << 1) | nt;
                BH[bi][0] = __float_as_uint(w0);
                BH[bi][1] = __float_as_uint(w1);
            }
        }

    // zero h buffer 0: 32768 halves = 16384 u32, 128 per CTA
    if (tid < 128) ((unsigned*)g_hbufh[0])[cta * 128 + tid] = 0u;

    {   // load x_proj(t=0) into sx[0]
        int b = tid >> 2, g = tid & 3;
        cp16(sx + b * 16 + g * 4,
             g_xproj + ((size_t)b << 11) + ((size_t)g << 9) + (cta << 2));
        asm volatile("cp.async.commit_group;" ::: "memory");
        asm volatile("cp.async.wait_group 0;" ::: "memory");
    }

    __syncthreads();
    {   // barrier 0: init complete
        unsigned tgt = base + 1;
        if (tid == 0) st_rel(&g_flags[cta * 32], tgt);
        if (tid < NCTA)
            while ((int)(ld_acq(&g_flags[tid * 32]) - tgt) < 0) {}
        __syncthreads();
    }

    const int eb = tid >> 2, ej = tid & 3;
    const int colj = (cta << 2) + ej;
    float c_reg = 0.f;

    // warp-local chunk copy into DEDICATED buffer ch.
    auto issue_chunk = [&](const __half* hsrc, int ch) {
#pragma unroll
        for (int j = 0; j < 2; j++) {
            const __half* s0 = hsrc + (size_t)(ch * 128 + j * 64 + warp * 8) * 64;
            __half* d0 = sh + ch * SHH_CHUNK + (j * 64 + warp * 8) * SHH_STRIDE;
#pragma unroll
            for (int i = 0; i < 2; i++) {
                int s_ = lane + 32 * i;            // 0..63
                int row8 = s_ >> 3, segc = s_ & 7;
                cp16(d0 + row8 * SHH_STRIDE + segc * 8, s0 + row8 * 64 + segc * 8);
            }
        }
        asm volatile("cp.async.commit_group;" ::: "memory");
    };

    for (int t = 0; t < T_; t++) {
        const __half* hsrc = g_hbufh[t & 1];

        // groups 0..3: h chunks; group 4: x_proj(t+1) prefetch (never waited
        // inside this step -> full step to cover DRAM latency)
        issue_chunk(hsrc, 0);
        issue_chunk(hsrc, 1);
        issue_chunk(hsrc, 2);
        issue_chunk(hsrc, 3);
        if (t + 1 < T_) {
            int b = tid >> 2, g = tid & 3;
            cp16(sx + ((t + 1) & 1) * 1024 + b * 16 + g * 4,
                 g_xproj + ((size_t)((t + 1) * 64 + b) << 11)
                         + ((size_t)g << 9) + (cta << 2));
        }
        asm volatile("cp.async.commit_group;" ::: "memory");

        float acc[4][2][4];
#pragma unroll
        for (int mt = 0; mt < 4; mt++)
#pragma unroll
            for (int nt = 0; nt < 2; nt++)
#pragma unroll
                for (int k = 0; k < 4; k++) acc[mt][nt][k] = 0.f;

#pragma unroll
        for (int ch = 0; ch < 4; ch++) {
            switch (ch) {   // wait only for this chunk's group (FIFO order)
                case 0: asm volatile("cp.async.wait_group 4;" ::: "memory"); break;
                case 1: asm volatile("cp.async.wait_group 3;" ::: "memory"); break;
                case 2: asm volatile("cp.async.wait_group 2;" ::: "memory"); break;
                default: asm volatile("cp.async.wait_group 1;" ::: "memory"); break;
            }
            __syncwarp();

            const __half* hb = sh + ch * SHH_CHUNK;
#pragma unroll
            for (int j = 0; j < 2; j++) {
                const int lk0 = ((j << 3) + warp) << 3;
                unsigned a[4][4];
#pragma unroll
                for (int mt = 0; mt < 4; mt++) {
                    const __half* ap = hb + (lk0 + cq) * SHH_STRIDE + mt * 16 + r;
                    a[mt][0] = __float_as_uint(__half2float(ap[0]));
                    a[mt][1] = __float_as_uint(__half2float(ap[8]));
                    a[mt][2] = __float_as_uint(__half2float(ap[4 * SHH_STRIDE]));
                    a[mt][3] = __float_as_uint(__half2float(ap[4 * SHH_STRIDE + 8]));
                }
                const int bi0 = (ch << 2) | (j << 1);
#pragma unroll
                for (int nt = 0; nt < 2; nt++)
#pragma unroll
                    for (int mt = 0; mt < 4; mt++)
                        mma8(acc[mt][nt], a[mt][0], a[mt][1], a[mt][2], a[mt][3],
                             BH[bi0 | nt][0], BH[bi0 | nt][1]);
            }
        }

        {
            float* sgp = sg + warp * SG_WARP;
#pragma unroll
            for (int mt = 0; mt < 4; mt++) {
                int b0 = mt * 16 + r;
#pragma unroll
                for (int nt = 0; nt < 2; nt++) {
                    int n = nt * 8 + cq * 2;
                    *(float2*)&sgp[b0 * SG_STRIDE + n] =
                        make_float2(acc[mt][nt][0], acc[mt][nt][1]);
                    *(float2*)&sgp[(b0 + 8) * SG_STRIDE + n] =
                        make_float2(acc[mt][nt][2], acc[mt][nt][3]);
                }
            }
        }
        __syncthreads();

        {
            const float* sxb = sx + (t & 1) * 1024;
            float v[4];
#pragma unroll
            for (int g = 0; g < 4; g++) {
                int n = (g << 2) + ej;
                float s = sxb[eb * 16 + n];
#pragma unroll
                for (int w = 0; w < 8; w++) s += sg[w * SG_WARP + eb * SG_STRIDE + n];
                v[g] = s;
            }
            float si = 1.f / (1.f + __expf(-v[0]));
            float sf = 1.f / (1.f + __expf(-v[1]));
            float tg = tanhf(v[2]);
            float so = 1.f / (1.f + __expf(-v[3]));
            c_reg = sf * c_reg + si * tg;
            float hn = so * tanhf(c_reg);

            g_hbufh[(t + 1) & 1][(colj << 6) + eb] = __float2half_rn(hn);

            if (t == T_ - 1) {
                out[eb * H_ + colj]           = c_reg;   // c_fin
                out[B_ * H_ + eb * H_ + colj] = hn;      // h_fin
            }
        }

        __syncthreads();
        {
            unsigned tgt = base + 2 + (unsigned)t;
            if (tid == 0) st_rel(&g_flags[cta * 32], tgt);
            if (tid < NCTA)
                while ((int)(ld_acq(&g_flags[tid * 32]) - tgt) < 0) {}
            __syncthreads();
        }
    }
}

// ---------------------------------------------------------------------------
extern "C" void kernel_launch(void* const* d_in, const int* in_sizes, int n_in,
                              void* d_out, int out_size)
{
    const float* inputs = (const float*)d_in[0];  // [B, T, F]
    const float* Wx     = (const float*)d_in[1];  // [F, 4H]
    const float* Wh     = (const float*)d_in[2];  // [H, 4H]
    const float* bias   = (const float*)d_in[3];  // [4H]
    float* out = (float*)d_out;                   // [2, B, H] = (c_fin, h_fin)

    (void)in_sizes; (void)n_in; (void)out_size;

    conv_a<<<8192, 256>>>(inputs);
    conv_b<<<4096, 256>>>(Wx);

    cudaFuncSetAttribute(gemm_f16, cudaFuncAttributeMaxDynamicSharedMemorySize, GSMEM);
    gemm_f16<<<dim3(G4_ / 128, (B_ * T_) / 128), 256, GSMEM>>>(bias);

    const int lstm_smem = 4 * SHH_CHUNK * 2 + 8 * SG_WARP * 4 + 2 * 1024 * 4; // 118784 B
    cudaFuncSetAttribute(lstm_kernel, cudaFuncAttributeMaxDynamicSharedMemorySize, lstm_smem);
    lstm_kernel<<<NCTA, 256, lstm_smem>>>(Wh, out);
}